// round 5
// baseline (speedup 1.0000x reference)
#include <cuda_runtime.h>
#include <cuda_bf16.h>
#include <cstdint>

typedef unsigned long long u64;

#define NROWS 200000
#define NTILES 3125          // 200000 / 64
#define BM 64
#define LDIM 480

// ============================ HMMA helpers ============================
__device__ __forceinline__ void mma_bf16(float& c0, float& c1, float& c2, float& c3,
                                         uint32_t a0, uint32_t a1, uint32_t a2, uint32_t a3,
                                         uint32_t b0, uint32_t b1)
{
    asm volatile("mma.sync.aligned.m16n8k16.row.col.f32.bf16.bf16.f32 "
                 "{%0,%1,%2,%3}, {%4,%5,%6,%7}, {%8,%9}, {%0,%1,%2,%3};"
                 : "+f"(c0), "+f"(c1), "+f"(c2), "+f"(c3)
                 : "r"(a0), "r"(a1), "r"(a2), "r"(a3), "r"(b0), "r"(b1));
}

__device__ __forceinline__ uint32_t pack_hi(float x, float y, float& rx, float& ry) {
    __nv_bfloat162 h = __float22bfloat162_rn(make_float2(x, y));
    float2 hf = __bfloat1622float2(h);
    rx = x - hf.x; ry = y - hf.y;
    return *(uint32_t*)&h;
}
__device__ __forceinline__ uint32_t pack_lo(float rx, float ry) {
    __nv_bfloat162 l = __float22bfloat162_rn(make_float2(rx, ry));
    return *(uint32_t*)&l;
}
__device__ __forceinline__ void split_bf16(float v, __nv_bfloat16& h, __nv_bfloat16& l) {
    h = __float2bfloat16(v);
    l = __float2bfloat16(v - __bfloat162float(h));
}

// ============================================================================
// Kernel 0 (HMMA, unchanged from passing R4): out[:, 0:128]
// ============================================================================
#define K0_STRIDE 136
#define K0_B0   0
#define K0_BH   512
#define K0_BL   35328
#define K0_AH   70144
#define K0_AL   87552
#define K0_SMEM 104960

__global__ void __launch_bounds__(256, 2)
k0_mma(const float* __restrict__ x, const float* __restrict__ w0,
       const float* __restrict__ b0, float* __restrict__ out)
{
    extern __shared__ char smem[];
    float* b0s = (float*)(smem + K0_B0);

    const int tid  = threadIdx.x;
    const int wid  = tid >> 5;
    const int lane = tid & 31;
    const float a0 = 0.08838834764831845f;   // 1/sqrt(128)

    for (int idx = tid; idx < 128 * 128; idx += 256) {
        int n = idx & 127, k = idx >> 7;
        float v = a0 * w0[k * 128 + n];
        __nv_bfloat16 h, l;
        split_bf16(v, h, l);
        *(__nv_bfloat16*)(smem + K0_BH + (n * K0_STRIDE + k) * 2) = h;
        *(__nv_bfloat16*)(smem + K0_BL + (n * K0_STRIDE + k) * 2) = l;
    }
    if (tid < 128) b0s[tid] = b0[tid];

    const int mt = wid >> 1;
    const int nh = wid & 1;
    const int ar = mt * 16 + (lane >> 2);
    const int ak = (lane & 3) * 2;
    const int bn = nh * 64 + (lane >> 2);
    const int ncol = nh * 64 + (lane & 3) * 2;

    __syncthreads();

    for (int t = blockIdx.x; t < NTILES; t += gridDim.x) {
        const int row0 = t * BM;

        #pragma unroll
        for (int i = tid; i < 64 * 32; i += 256) {
            int r = i >> 5, c4 = (i & 31) << 2;
            float4 v = *(const float4*)(x + (size_t)(row0 + r) * LDIM + c4);
            float rx, ry, rz, rw;
            uint32_t h0 = pack_hi(v.x, v.y, rx, ry);
            uint32_t h1 = pack_hi(v.z, v.w, rz, rw);
            uint32_t l0 = pack_lo(rx, ry);
            uint32_t l1 = pack_lo(rz, rw);
            uint32_t off = (uint32_t)(r * K0_STRIDE + c4) * 2u;
            *(uint2*)(smem + K0_AH + off) = make_uint2(h0, h1);
            *(uint2*)(smem + K0_AL + off) = make_uint2(l0, l1);
        }
        __syncthreads();

        uint32_t ah[8][4], al[8][4];
        {
            const uint32_t base = (uint32_t)(ar * K0_STRIDE + ak) * 2u;
            #pragma unroll
            for (int ks = 0; ks < 8; ks++) {
                uint32_t o = base + (uint32_t)(ks * 16) * 2u;
                ah[ks][0] = *(const uint32_t*)(smem + K0_AH + o);
                ah[ks][1] = *(const uint32_t*)(smem + K0_AH + o + 8 * K0_STRIDE * 2);
                ah[ks][2] = *(const uint32_t*)(smem + K0_AH + o + 16);
                ah[ks][3] = *(const uint32_t*)(smem + K0_AH + o + 8 * K0_STRIDE * 2 + 16);
                al[ks][0] = *(const uint32_t*)(smem + K0_AL + o);
                al[ks][1] = *(const uint32_t*)(smem + K0_AL + o + 8 * K0_STRIDE * 2);
                al[ks][2] = *(const uint32_t*)(smem + K0_AL + o + 16);
                al[ks][3] = *(const uint32_t*)(smem + K0_AL + o + 8 * K0_STRIDE * 2 + 16);
            }
        }

        #pragma unroll
        for (int nt = 0; nt < 8; nt++) {
            float c0 = b0s[ncol + nt * 8];
            float c1 = b0s[ncol + nt * 8 + 1];
            float c2 = c0, c3 = c1;
            const uint32_t bbase = (uint32_t)((bn + nt * 8) * K0_STRIDE + ak) * 2u;
            #pragma unroll
            for (int ks = 0; ks < 8; ks++) {
                uint32_t o = bbase + (uint32_t)(ks * 16) * 2u;
                uint32_t bh0 = *(const uint32_t*)(smem + K0_BH + o);
                uint32_t bh1 = *(const uint32_t*)(smem + K0_BH + o + 16);
                uint32_t bl0 = *(const uint32_t*)(smem + K0_BL + o);
                uint32_t bl1 = *(const uint32_t*)(smem + K0_BL + o + 16);
                mma_bf16(c0, c1, c2, c3, ah[ks][0], ah[ks][1], ah[ks][2], ah[ks][3], bh0, bh1);
                mma_bf16(c0, c1, c2, c3, al[ks][0], al[ks][1], al[ks][2], al[ks][3], bh0, bh1);
                mma_bf16(c0, c1, c2, c3, ah[ks][0], ah[ks][1], ah[ks][2], ah[ks][3], bl0, bl1);
            }
            const int grow = row0 + mt * 16 + (lane >> 2);
            float* o0 = out + (size_t)grow * LDIM + ncol + nt * 8;
            *(float2*)o0              = make_float2(c0, c1);
            *(float2*)(o0 + 8 * LDIM) = make_float2(c2, c3);
        }
        __syncthreads();
    }
}

// ============================================================================
// Kernel 1 (HMMA): out[:, 128+3w+i] = sum_u x[:,128+3u+i] * (a1*w1[u,w]), i=0..2
// 3 channels, each a 64-row x [64x64] GEMM; B shared across channels.
// smem: Bh[0,9216) Bl[9216,18432) Ah[18432,46080) Al[46080,73728)
// A/B bf16 row stride 72 -> fragment lds conflict-free ((4r+kp) mod 32).
// ============================================================================
#define K1_ST 72
#define K1_BH 0
#define K1_BL 9216
#define K1_AH 18432
#define K1_AL 46080
#define K1_ABLK 9216          // per-channel A block bytes (64*72*2)
#define K1_SMEM 73728

__global__ void __launch_bounds__(256, 2)
k1_mma(const float* __restrict__ x, const float* __restrict__ w1,
       float* __restrict__ out)
{
    extern __shared__ char smem[];
    const int tid  = threadIdx.x;
    const int wid  = tid >> 5;
    const int lane = tid & 31;
    const float a1 = 0.125f;   // 1/sqrt(64)

    // stage B: B[n=w][k=u] = a1*w1[u][w]
    for (int idx = tid; idx < 64 * 64; idx += 256) {
        int u = idx >> 6, w = idx & 63;
        float v = a1 * w1[idx];
        __nv_bfloat16 h, l;
        split_bf16(v, h, l);
        *(__nv_bfloat16*)(smem + K1_BH + (w * K1_ST + u) * 2) = h;
        *(__nv_bfloat16*)(smem + K1_BL + (w * K1_ST + u) * 2) = l;
    }

    const int mt = wid >> 1;                 // m-tile 0..3
    const int nh = wid & 1;                  // n-half: nt in {4nh..4nh+3}
    const int ar = mt * 16 + (lane >> 2);
    const int ak = (lane & 3) * 2;
    const int bn = lane >> 2;                // n within tile
    const int np = (lane & 3) * 2;           // n col pair base within n-tile

    for (int t = blockIdx.x; t < NTILES; t += gridDim.x) {
        const int row0 = t * BM;
        __syncthreads();

        // stage A: channel-deinterleave x[:,128..320) -> Ah/Al[ch][64][64]
        #pragma unroll
        for (int i = tid; i < 64 * 48; i += 256) {
            int r = i / 48, c4 = (i - r * 48) * 4;
            float4 v = *(const float4*)(x + (size_t)(row0 + r) * LDIM + 128 + c4);
            float f[4] = {v.x, v.y, v.z, v.w};
            #pragma unroll
            for (int j = 0; j < 4; j++) {
                int c = c4 + j;
                int ch = c % 3, u = c / 3;
                __nv_bfloat16 h, l;
                split_bf16(f[j], h, l);
                uint32_t o = (uint32_t)(ch * K1_ABLK) + (uint32_t)(r * K1_ST + u) * 2u;
                *(__nv_bfloat16*)(smem + K1_AH + o) = h;
                *(__nv_bfloat16*)(smem + K1_AL + o) = l;
            }
        }
        __syncthreads();

        #pragma unroll 1
        for (int ch = 0; ch < 3; ch++) {
            const uint32_t abase = (uint32_t)(ch * K1_ABLK) + (uint32_t)(ar * K1_ST + ak) * 2u;
            uint32_t ah[4][4], al[4][4];
            #pragma unroll
            for (int ks = 0; ks < 4; ks++) {
                uint32_t o = abase + (uint32_t)(ks * 16) * 2u;
                ah[ks][0] = *(const uint32_t*)(smem + K1_AH + o);
                ah[ks][1] = *(const uint32_t*)(smem + K1_AH + o + 8 * K1_ST * 2);
                ah[ks][2] = *(const uint32_t*)(smem + K1_AH + o + 16);
                ah[ks][3] = *(const uint32_t*)(smem + K1_AH + o + 8 * K1_ST * 2 + 16);
                al[ks][0] = *(const uint32_t*)(smem + K1_AL + o);
                al[ks][1] = *(const uint32_t*)(smem + K1_AL + o + 8 * K1_ST * 2);
                al[ks][2] = *(const uint32_t*)(smem + K1_AL + o + 16);
                al[ks][3] = *(const uint32_t*)(smem + K1_AL + o + 8 * K1_ST * 2 + 16);
            }
            #pragma unroll
            for (int q = 0; q < 4; q++) {
                const int nt = nh * 4 + q;
                float c0 = 0.f, c1 = 0.f, c2 = 0.f, c3 = 0.f;
                const uint32_t bbase = (uint32_t)((bn + nt * 8) * K1_ST + ak) * 2u;
                #pragma unroll
                for (int ks = 0; ks < 4; ks++) {
                    uint32_t o = bbase + (uint32_t)(ks * 16) * 2u;
                    uint32_t bh0 = *(const uint32_t*)(smem + K1_BH + o);
                    uint32_t bh1 = *(const uint32_t*)(smem + K1_BH + o + 16);
                    uint32_t bl0 = *(const uint32_t*)(smem + K1_BL + o);
                    uint32_t bl1 = *(const uint32_t*)(smem + K1_BL + o + 16);
                    mma_bf16(c0, c1, c2, c3, ah[ks][0], ah[ks][1], ah[ks][2], ah[ks][3], bh0, bh1);
                    mma_bf16(c0, c1, c2, c3, al[ks][0], al[ks][1], al[ks][2], al[ks][3], bh0, bh1);
                    mma_bf16(c0, c1, c2, c3, ah[ks][0], ah[ks][1], ah[ks][2], ah[ks][3], bl0, bl1);
                }
                const int grow = row0 + mt * 16 + (lane >> 2);
                const int n0 = nt * 8 + np;
                float* o0 = out + (size_t)grow * LDIM + 128 + 3 * n0 + ch;
                o0[0] = c0;  o0[3] = c1;
                o0[8 * LDIM] = c2;  o0[8 * LDIM + 3] = c3;
            }
        }
    }
}

// ============================================================================
// Kernel 2 (HMMA): out[:, 320+5w+i] = sum_u x[:,320+5u+i] * (a2*w2[u,w]), i=0..4
// 5 channels, each a 64-row x [32x32] GEMM; B shared across channels.
// smem: Bh[0,2560) Bl[2560,5120) Ah[5120,30720) Al[30720,56320)
// stride 40 -> fragment lds conflict-free ((20r+kp) mod 32 distinct).
// ============================================================================
#define K2_ST 40
#define K2_BH 0
#define K2_BL 2560
#define K2_AH 5120
#define K2_AL 30720
#define K2_ABLK 5120          // per-channel A block bytes (64*40*2)
#define K2_SMEM 56320

__global__ void __launch_bounds__(256, 3)
k2_mma(const float* __restrict__ x, const float* __restrict__ w2,
       float* __restrict__ out)
{
    extern __shared__ char smem[];
    const int tid  = threadIdx.x;
    const int wid  = tid >> 5;
    const int lane = tid & 31;
    const float a2 = 0.17677669529663687f;  // 1/sqrt(32)

    for (int idx = tid; idx < 32 * 32; idx += 256) {
        int u = idx >> 5, w = idx & 31;
        float v = a2 * w2[idx];
        __nv_bfloat16 h, l;
        split_bf16(v, h, l);
        *(__nv_bfloat16*)(smem + K2_BH + (w * K2_ST + u) * 2) = h;
        *(__nv_bfloat16*)(smem + K2_BL + (w * K2_ST + u) * 2) = l;
    }

    const int mt = wid >> 1;
    const int nh = wid & 1;                  // nt in {2nh, 2nh+1}
    const int ar = mt * 16 + (lane >> 2);
    const int ak = (lane & 3) * 2;
    const int bn = lane >> 2;
    const int np = (lane & 3) * 2;

    for (int t = blockIdx.x; t < NTILES; t += gridDim.x) {
        const int row0 = t * BM;
        __syncthreads();

        // stage A: channel-deinterleave x[:,320..480) -> Ah/Al[ch][64][32]
        #pragma unroll
        for (int i = tid; i < 64 * 40; i += 256) {
            int r = i / 40, c4 = (i - r * 40) * 4;
            float4 v = *(const float4*)(x + (size_t)(row0 + r) * LDIM + 320 + c4);
            float f[4] = {v.x, v.y, v.z, v.w};
            #pragma unroll
            for (int j = 0; j < 4; j++) {
                int c = c4 + j;
                int ch = c % 5, u = c / 5;
                __nv_bfloat16 h, l;
                split_bf16(f[j], h, l);
                uint32_t o = (uint32_t)(ch * K2_ABLK) + (uint32_t)(r * K2_ST + u) * 2u;
                *(__nv_bfloat16*)(smem + K2_AH + o) = h;
                *(__nv_bfloat16*)(smem + K2_AL + o) = l;
            }
        }
        __syncthreads();

        #pragma unroll 1
        for (int ch = 0; ch < 5; ch++) {
            const uint32_t abase = (uint32_t)(ch * K2_ABLK) + (uint32_t)(ar * K2_ST + ak) * 2u;
            uint32_t ah[2][4], al[2][4];
            #pragma unroll
            for (int ks = 0; ks < 2; ks++) {
                uint32_t o = abase + (uint32_t)(ks * 16) * 2u;
                ah[ks][0] = *(const uint32_t*)(smem + K2_AH + o);
                ah[ks][1] = *(const uint32_t*)(smem + K2_AH + o + 8 * K2_ST * 2);
                ah[ks][2] = *(const uint32_t*)(smem + K2_AH + o + 16);
                ah[ks][3] = *(const uint32_t*)(smem + K2_AH + o + 8 * K2_ST * 2 + 16);
                al[ks][0] = *(const uint32_t*)(smem + K2_AL + o);
                al[ks][1] = *(const uint32_t*)(smem + K2_AL + o + 8 * K2_ST * 2);
                al[ks][2] = *(const uint32_t*)(smem + K2_AL + o + 16);
                al[ks][3] = *(const uint32_t*)(smem + K2_AL + o + 8 * K2_ST * 2 + 16);
            }
            #pragma unroll
            for (int q = 0; q < 2; q++) {
                const int nt = nh * 2 + q;
                float c0 = 0.f, c1 = 0.f, c2 = 0.f, c3 = 0.f;
                const uint32_t bbase = (uint32_t)((bn + nt * 8) * K2_ST + ak) * 2u;
                #pragma unroll
                for (int ks = 0; ks < 2; ks++) {
                    uint32_t o = bbase + (uint32_t)(ks * 16) * 2u;
                    uint32_t bh0 = *(const uint32_t*)(smem + K2_BH + o);
                    uint32_t bh1 = *(const uint32_t*)(smem + K2_BH + o + 16);
                    uint32_t bl0 = *(const uint32_t*)(smem + K2_BL + o);
                    uint32_t bl1 = *(const uint32_t*)(smem + K2_BL + o + 16);
                    mma_bf16(c0, c1, c2, c3, ah[ks][0], ah[ks][1], ah[ks][2], ah[ks][3], bh0, bh1);
                    mma_bf16(c0, c1, c2, c3, al[ks][0], al[ks][1], al[ks][2], al[ks][3], bh0, bh1);
                    mma_bf16(c0, c1, c2, c3, ah[ks][0], ah[ks][1], ah[ks][2], ah[ks][3], bl0, bl1);
                }
                const int grow = row0 + mt * 16 + (lane >> 2);
                const int n0 = nt * 8 + np;
                float* o0 = out + (size_t)grow * LDIM + 320 + 5 * n0 + ch;
                o0[0] = c0;  o0[5] = c1;
                o0[8 * LDIM] = c2;  o0[8 * LDIM + 5] = c3;
            }
        }
    }
}

// ============================================================================

extern "C" void kernel_launch(void* const* d_in, const int* in_sizes, int n_in,
                              void* d_out, int out_size)
{
    const float* x  = (const float*)d_in[0];
    const float* w0 = (const float*)d_in[1];
    const float* w1 = (const float*)d_in[2];
    const float* w2 = (const float*)d_in[3];
    const float* b0 = (const float*)d_in[4];
    float* out = (float*)d_out;

    cudaFuncSetAttribute(k0_mma, cudaFuncAttributeMaxDynamicSharedMemorySize, K0_SMEM);
    cudaFuncSetAttribute(k1_mma, cudaFuncAttributeMaxDynamicSharedMemorySize, K1_SMEM);
    cudaFuncSetAttribute(k2_mma, cudaFuncAttributeMaxDynamicSharedMemorySize, K2_SMEM);

    k0_mma<<<304, 256, K0_SMEM>>>(x, w0, b0, out);
    k1_mma<<<304, 256, K1_SMEM>>>(x, w1, out);
    k2_mma<<<456, 256, K2_SMEM>>>(x, w2, out);
}

// round 6
// speedup vs baseline: 1.5742x; 1.5742x over previous
#include <cuda_runtime.h>
#include <cuda_bf16.h>
#include <cstdint>

#define NROWS 200000
#define NTILES 3125          // 200000 / 64
#define BM 64
#define LDIM 480

// ============================ HMMA helpers ============================
__device__ __forceinline__ void mma_bf16(float& c0, float& c1, float& c2, float& c3,
                                         uint32_t a0, uint32_t a1, uint32_t a2, uint32_t a3,
                                         uint32_t b0, uint32_t b1)
{
    asm volatile("mma.sync.aligned.m16n8k16.row.col.f32.bf16.bf16.f32 "
                 "{%0,%1,%2,%3}, {%4,%5,%6,%7}, {%8,%9}, {%0,%1,%2,%3};"
                 : "+f"(c0), "+f"(c1), "+f"(c2), "+f"(c3)
                 : "r"(a0), "r"(a1), "r"(a2), "r"(a3), "r"(b0), "r"(b1));
}

__device__ __forceinline__ uint32_t pack_hi(float x, float y, float& rx, float& ry) {
    __nv_bfloat162 h = __float22bfloat162_rn(make_float2(x, y));
    float2 hf = __bfloat1622float2(h);
    rx = x - hf.x; ry = y - hf.y;
    return *(uint32_t*)&h;
}
__device__ __forceinline__ uint32_t pack_lo(float rx, float ry) {
    __nv_bfloat162 l = __float22bfloat162_rn(make_float2(rx, ry));
    return *(uint32_t*)&l;
}
__device__ __forceinline__ void split_bf16(float v, __nv_bfloat16& h, __nv_bfloat16& l) {
    h = __float2bfloat16(v);
    l = __float2bfloat16(v - __bfloat162float(h));
}
// pack 4 bf16 (hi) + 4 bf16 (lo) from 4 floats
__device__ __forceinline__ void split4(const float* f, uint2& hi, uint2& lo) {
    float r0, r1, r2, r3;
    uint32_t h0 = pack_hi(f[0], f[1], r0, r1);
    uint32_t h1 = pack_hi(f[2], f[3], r2, r3);
    hi = make_uint2(h0, h1);
    lo = make_uint2(pack_lo(r0, r1), pack_lo(r2, r3));
}

// ============================================================================
// Kernel 0 (HMMA, unchanged from passing R4): out[:, 0:128]
// ============================================================================
#define K0_STRIDE 136
#define K0_B0   0
#define K0_BH   512
#define K0_BL   35328
#define K0_AH   70144
#define K0_AL   87552
#define K0_SMEM 104960

__global__ void __launch_bounds__(256, 2)
k0_mma(const float* __restrict__ x, const float* __restrict__ w0,
       const float* __restrict__ b0, float* __restrict__ out)
{
    extern __shared__ char smem[];
    float* b0s = (float*)(smem + K0_B0);

    const int tid  = threadIdx.x;
    const int wid  = tid >> 5;
    const int lane = tid & 31;
    const float a0 = 0.08838834764831845f;   // 1/sqrt(128)

    for (int idx = tid; idx < 128 * 128; idx += 256) {
        int n = idx & 127, k = idx >> 7;
        float v = a0 * w0[k * 128 + n];
        __nv_bfloat16 h, l;
        split_bf16(v, h, l);
        *(__nv_bfloat16*)(smem + K0_BH + (n * K0_STRIDE + k) * 2) = h;
        *(__nv_bfloat16*)(smem + K0_BL + (n * K0_STRIDE + k) * 2) = l;
    }
    if (tid < 128) b0s[tid] = b0[tid];

    const int mt = wid >> 1;
    const int nh = wid & 1;
    const int ar = mt * 16 + (lane >> 2);
    const int ak = (lane & 3) * 2;
    const int bn = nh * 64 + (lane >> 2);
    const int ncol = nh * 64 + (lane & 3) * 2;

    __syncthreads();

    for (int t = blockIdx.x; t < NTILES; t += gridDim.x) {
        const int row0 = t * BM;

        #pragma unroll
        for (int i = tid; i < 64 * 32; i += 256) {
            int r = i >> 5, c4 = (i & 31) << 2;
            float4 v = *(const float4*)(x + (size_t)(row0 + r) * LDIM + c4);
            float rx, ry, rz, rw;
            uint32_t h0 = pack_hi(v.x, v.y, rx, ry);
            uint32_t h1 = pack_hi(v.z, v.w, rz, rw);
            uint32_t l0 = pack_lo(rx, ry);
            uint32_t l1 = pack_lo(rz, rw);
            uint32_t off = (uint32_t)(r * K0_STRIDE + c4) * 2u;
            *(uint2*)(smem + K0_AH + off) = make_uint2(h0, h1);
            *(uint2*)(smem + K0_AL + off) = make_uint2(l0, l1);
        }
        __syncthreads();

        uint32_t ah[8][4], al[8][4];
        {
            const uint32_t base = (uint32_t)(ar * K0_STRIDE + ak) * 2u;
            #pragma unroll
            for (int ks = 0; ks < 8; ks++) {
                uint32_t o = base + (uint32_t)(ks * 16) * 2u;
                ah[ks][0] = *(const uint32_t*)(smem + K0_AH + o);
                ah[ks][1] = *(const uint32_t*)(smem + K0_AH + o + 8 * K0_STRIDE * 2);
                ah[ks][2] = *(const uint32_t*)(smem + K0_AH + o + 16);
                ah[ks][3] = *(const uint32_t*)(smem + K0_AH + o + 8 * K0_STRIDE * 2 + 16);
                al[ks][0] = *(const uint32_t*)(smem + K0_AL + o);
                al[ks][1] = *(const uint32_t*)(smem + K0_AL + o + 8 * K0_STRIDE * 2);
                al[ks][2] = *(const uint32_t*)(smem + K0_AL + o + 16);
                al[ks][3] = *(const uint32_t*)(smem + K0_AL + o + 8 * K0_STRIDE * 2 + 16);
            }
        }

        #pragma unroll
        for (int nt = 0; nt < 8; nt++) {
            float c0 = b0s[ncol + nt * 8];
            float c1 = b0s[ncol + nt * 8 + 1];
            float c2 = c0, c3 = c1;
            const uint32_t bbase = (uint32_t)((bn + nt * 8) * K0_STRIDE + ak) * 2u;
            #pragma unroll
            for (int ks = 0; ks < 8; ks++) {
                uint32_t o = bbase + (uint32_t)(ks * 16) * 2u;
                uint32_t bh0 = *(const uint32_t*)(smem + K0_BH + o);
                uint32_t bh1 = *(const uint32_t*)(smem + K0_BH + o + 16);
                uint32_t bl0 = *(const uint32_t*)(smem + K0_BL + o);
                uint32_t bl1 = *(const uint32_t*)(smem + K0_BL + o + 16);
                mma_bf16(c0, c1, c2, c3, ah[ks][0], ah[ks][1], ah[ks][2], ah[ks][3], bh0, bh1);
                mma_bf16(c0, c1, c2, c3, al[ks][0], al[ks][1], al[ks][2], al[ks][3], bh0, bh1);
                mma_bf16(c0, c1, c2, c3, ah[ks][0], ah[ks][1], ah[ks][2], ah[ks][3], bl0, bl1);
            }
            const int grow = row0 + mt * 16 + (lane >> 2);
            float* o0 = out + (size_t)grow * LDIM + ncol + nt * 8;
            *(float2*)o0              = make_float2(c0, c1);
            *(float2*)(o0 + 8 * LDIM) = make_float2(c2, c3);
        }
        __syncthreads();
    }
}

// ============================================================================
// Kernel 1 (HMMA + coalesced epilogue): out[:, 128+3w+i]
// smem: Bh[0,9216) Bl[9216,18432) Ah[18432,46080) Al[46080,73728)
// out-stage OVERLAYS Ah/Al: [64][196] floats = 50176 B at offset 18432.
// C kept in regs (48) across channels; staging vectorized (STS.64 of 4 bf16).
// ============================================================================
#define K1_ST 72
#define K1_BH 0
#define K1_BL 9216
#define K1_AH 18432
#define K1_AL 46080
#define K1_ABLK 9216
#define K1_OUT 18432          // overlay on Ah/Al
#define K1_OST 196            // out-stage row stride (floats)
#define K1_SMEM 73728

__global__ void __launch_bounds__(256, 2)
k1_mma(const float* __restrict__ x, const float* __restrict__ w1,
       float* __restrict__ out)
{
    extern __shared__ char smem[];
    const int tid  = threadIdx.x;
    const int wid  = tid >> 5;
    const int lane = tid & 31;
    const float a1 = 0.125f;   // 1/sqrt(64)

    for (int idx = tid; idx < 64 * 64; idx += 256) {
        int u = idx >> 6, w = idx & 63;
        float v = a1 * w1[idx];
        __nv_bfloat16 h, l;
        split_bf16(v, h, l);
        *(__nv_bfloat16*)(smem + K1_BH + (w * K1_ST + u) * 2) = h;
        *(__nv_bfloat16*)(smem + K1_BL + (w * K1_ST + u) * 2) = l;
    }

    const int mt = wid >> 1;
    const int nh = wid & 1;
    const int ar = mt * 16 + (lane >> 2);
    const int ak = (lane & 3) * 2;
    const int bn = lane >> 2;
    const int np = (lane & 3) * 2;

    for (int t = blockIdx.x; t < NTILES; t += gridDim.x) {
        const int row0 = t * BM;
        __syncthreads();   // prior readout done before staging overwrites overlay

        // ---- stage A: thread owns (row r, 12-col group g); 4 iters ----
        #pragma unroll
        for (int it = 0; it < 4; it++) {
            int i = tid + it * 256;
            int r = i >> 4, g = i & 15;
            const float* xp = x + (size_t)(row0 + r) * LDIM + 128 + g * 12;
            float f[12];
            *(float4*)(f)     = *(const float4*)(xp);
            *(float4*)(f + 4) = *(const float4*)(xp + 4);
            *(float4*)(f + 8) = *(const float4*)(xp + 8);
            #pragma unroll
            for (int ch = 0; ch < 3; ch++) {
                float g4[4] = {f[ch], f[ch + 3], f[ch + 6], f[ch + 9]};
                uint2 hi, lo;
                split4(g4, hi, lo);
                uint32_t o = (uint32_t)(ch * K1_ABLK) + (uint32_t)(r * K1_ST + 4 * g) * 2u;
                *(uint2*)(smem + K1_AH + o) = hi;
                *(uint2*)(smem + K1_AL + o) = lo;
            }
        }
        __syncthreads();

        // ---- MMA: all C in registers ----
        float C[3][4][4];
        #pragma unroll
        for (int ch = 0; ch < 3; ch++) {
            const uint32_t abase = (uint32_t)(ch * K1_ABLK) + (uint32_t)(ar * K1_ST + ak) * 2u;
            uint32_t ah[4][4], al[4][4];
            #pragma unroll
            for (int ks = 0; ks < 4; ks++) {
                uint32_t o = abase + (uint32_t)(ks * 16) * 2u;
                ah[ks][0] = *(const uint32_t*)(smem + K1_AH + o);
                ah[ks][1] = *(const uint32_t*)(smem + K1_AH + o + 8 * K1_ST * 2);
                ah[ks][2] = *(const uint32_t*)(smem + K1_AH + o + 16);
                ah[ks][3] = *(const uint32_t*)(smem + K1_AH + o + 8 * K1_ST * 2 + 16);
                al[ks][0] = *(const uint32_t*)(smem + K1_AL + o);
                al[ks][1] = *(const uint32_t*)(smem + K1_AL + o + 8 * K1_ST * 2);
                al[ks][2] = *(const uint32_t*)(smem + K1_AL + o + 16);
                al[ks][3] = *(const uint32_t*)(smem + K1_AL + o + 8 * K1_ST * 2 + 16);
            }
            #pragma unroll
            for (int q = 0; q < 4; q++) {
                const int nt = nh * 4 + q;
                float c0 = 0.f, c1 = 0.f, c2 = 0.f, c3 = 0.f;
                const uint32_t bbase = (uint32_t)((bn + nt * 8) * K1_ST + ak) * 2u;
                #pragma unroll
                for (int ks = 0; ks < 4; ks++) {
                    uint32_t o = bbase + (uint32_t)(ks * 16) * 2u;
                    uint32_t bh0 = *(const uint32_t*)(smem + K1_BH + o);
                    uint32_t bh1 = *(const uint32_t*)(smem + K1_BH + o + 16);
                    uint32_t bl0 = *(const uint32_t*)(smem + K1_BL + o);
                    uint32_t bl1 = *(const uint32_t*)(smem + K1_BL + o + 16);
                    mma_bf16(c0, c1, c2, c3, ah[ks][0], ah[ks][1], ah[ks][2], ah[ks][3], bh0, bh1);
                    mma_bf16(c0, c1, c2, c3, al[ks][0], al[ks][1], al[ks][2], al[ks][3], bh0, bh1);
                    mma_bf16(c0, c1, c2, c3, ah[ks][0], ah[ks][1], ah[ks][2], ah[ks][3], bl0, bl1);
                }
                C[ch][q][0] = c0; C[ch][q][1] = c1; C[ch][q][2] = c2; C[ch][q][3] = c3;
            }
        }
        __syncthreads();   // A region free -> becomes out-stage

        // ---- write C into out-stage [64][196] ----
        {
            float* st = (float*)(smem + K1_OUT);
            const int rA = mt * 16 + (lane >> 2);
            #pragma unroll
            for (int ch = 0; ch < 3; ch++) {
                #pragma unroll
                for (int q = 0; q < 4; q++) {
                    const int n0 = (nh * 4 + q) * 8 + np;
                    const int col = 3 * n0 + ch;
                    st[rA * K1_OST + col]           = C[ch][q][0];
                    st[rA * K1_OST + col + 3]       = C[ch][q][1];
                    st[(rA + 8) * K1_OST + col]     = C[ch][q][2];
                    st[(rA + 8) * K1_OST + col + 3] = C[ch][q][3];
                }
            }
        }
        __syncthreads();

        // ---- coalesced store: 64 x 192 floats ----
        {
            const float* st = (const float*)(smem + K1_OUT);
            #pragma unroll
            for (int it = 0; it < 12; it++) {
                int i = tid + it * 256;
                int r = i / 48, c4 = (i - r * 48) * 4;
                float4 v = *(const float4*)(st + r * K1_OST + c4);
                *(float4*)(out + (size_t)(row0 + r) * LDIM + 128 + c4) = v;
            }
        }
    }
}

// ============================================================================
// Kernel 2 (HMMA + coalesced epilogue): out[:, 320+5w+i]
// smem: Bh[0,2560) Bl[2560,5120) Ah[5120,30720) Al[30720,56320)
//       OUT[56320, 98304): [64][164] floats (disjoint -> immediate C STS ok)
// ============================================================================
#define K2_ST 40
#define K2_BH 0
#define K2_BL 2560
#define K2_AH 5120
#define K2_AL 30720
#define K2_ABLK 5120
#define K2_OUT 56320
#define K2_OST 164
#define K2_SMEM 98304

__global__ void __launch_bounds__(256, 2)
k2_mma(const float* __restrict__ x, const float* __restrict__ w2,
       float* __restrict__ out)
{
    extern __shared__ char smem[];
    const int tid  = threadIdx.x;
    const int wid  = tid >> 5;
    const int lane = tid & 31;
    const float a2 = 0.17677669529663687f;  // 1/sqrt(32)

    for (int idx = tid; idx < 32 * 32; idx += 256) {
        int u = idx >> 5, w = idx & 31;
        float v = a2 * w2[idx];
        __nv_bfloat16 h, l;
        split_bf16(v, h, l);
        *(__nv_bfloat16*)(smem + K2_BH + (w * K2_ST + u) * 2) = h;
        *(__nv_bfloat16*)(smem + K2_BL + (w * K2_ST + u) * 2) = l;
    }

    const int mt = wid >> 1;
    const int nh = wid & 1;
    const int ar = mt * 16 + (lane >> 2);
    const int ak = (lane & 3) * 2;
    const int bn = lane >> 2;
    const int np = (lane & 3) * 2;
    float* st = (float*)(smem + K2_OUT);

    for (int t = blockIdx.x; t < NTILES; t += gridDim.x) {
        const int row0 = t * BM;
        __syncthreads();

        // ---- stage A: thread owns (row r, 20-col group g); 2 iters ----
        #pragma unroll
        for (int it = 0; it < 2; it++) {
            int i = tid + it * 256;
            int r = i >> 3, g = i & 7;
            const float* xp = x + (size_t)(row0 + r) * LDIM + 320 + g * 20;
            float f[20];
            #pragma unroll
            for (int q = 0; q < 5; q++)
                *(float4*)(f + 4 * q) = *(const float4*)(xp + 4 * q);
            #pragma unroll
            for (int ch = 0; ch < 5; ch++) {
                float g4[4] = {f[ch], f[ch + 5], f[ch + 10], f[ch + 15]};
                uint2 hi, lo;
                split4(g4, hi, lo);
                uint32_t o = (uint32_t)(ch * K2_ABLK) + (uint32_t)(r * K2_ST + 4 * g) * 2u;
                *(uint2*)(smem + K2_AH + o) = hi;
                *(uint2*)(smem + K2_AL + o) = lo;
            }
        }
        __syncthreads();

        // ---- MMA with immediate C STS into disjoint out-stage ----
        const int rA = mt * 16 + (lane >> 2);
        #pragma unroll
        for (int ch = 0; ch < 5; ch++) {
            const uint32_t abase = (uint32_t)(ch * K2_ABLK) + (uint32_t)(ar * K2_ST + ak) * 2u;
            uint32_t ah[2][4], al[2][4];
            #pragma unroll
            for (int ks = 0; ks < 2; ks++) {
                uint32_t o = abase + (uint32_t)(ks * 16) * 2u;
                ah[ks][0] = *(const uint32_t*)(smem + K2_AH + o);
                ah[ks][1] = *(const uint32_t*)(smem + K2_AH + o + 8 * K2_ST * 2);
                ah[ks][2] = *(const uint32_t*)(smem + K2_AH + o + 16);
                ah[ks][3] = *(const uint32_t*)(smem + K2_AH + o + 8 * K2_ST * 2 + 16);
                al[ks][0] = *(const uint32_t*)(smem + K2_AL + o);
                al[ks][1] = *(const uint32_t*)(smem + K2_AL + o + 8 * K2_ST * 2);
                al[ks][2] = *(const uint32_t*)(smem + K2_AL + o + 16);
                al[ks][3] = *(const uint32_t*)(smem + K2_AL + o + 8 * K2_ST * 2 + 16);
            }
            #pragma unroll
            for (int q = 0; q < 2; q++) {
                const int nt = nh * 2 + q;
                float c0 = 0.f, c1 = 0.f, c2 = 0.f, c3 = 0.f;
                const uint32_t bbase = (uint32_t)((bn + nt * 8) * K2_ST + ak) * 2u;
                #pragma unroll
                for (int ks = 0; ks < 2; ks++) {
                    uint32_t o = bbase + (uint32_t)(ks * 16) * 2u;
                    uint32_t bh0 = *(const uint32_t*)(smem + K2_BH + o);
                    uint32_t bh1 = *(const uint32_t*)(smem + K2_BH + o + 16);
                    uint32_t bl0 = *(const uint32_t*)(smem + K2_BL + o);
                    uint32_t bl1 = *(const uint32_t*)(smem + K2_BL + o + 16);
                    mma_bf16(c0, c1, c2, c3, ah[ks][0], ah[ks][1], ah[ks][2], ah[ks][3], bh0, bh1);
                    mma_bf16(c0, c1, c2, c3, al[ks][0], al[ks][1], al[ks][2], al[ks][3], bh0, bh1);
                    mma_bf16(c0, c1, c2, c3, ah[ks][0], ah[ks][1], ah[ks][2], ah[ks][3], bl0, bl1);
                }
                const int n0 = nt * 8 + np;
                const int col = 5 * n0 + ch;
                st[rA * K2_OST + col]           = c0;
                st[rA * K2_OST + col + 5]       = c1;
                st[(rA + 8) * K2_OST + col]     = c2;
                st[(rA + 8) * K2_OST + col + 5] = c3;
            }
        }
        __syncthreads();

        // ---- coalesced store: 64 x 160 floats ----
        #pragma unroll
        for (int it = 0; it < 10; it++) {
            int i = tid + it * 256;
            int r = i / 40, c4 = (i - r * 40) * 4;
            float4 v = *(const float4*)(st + r * K2_OST + c4);
            *(float4*)(out + (size_t)(row0 + r) * LDIM + 320 + c4) = v;
        }
    }
}

// ============================================================================

extern "C" void kernel_launch(void* const* d_in, const int* in_sizes, int n_in,
                              void* d_out, int out_size)
{
    const float* x  = (const float*)d_in[0];
    const float* w0 = (const float*)d_in[1];
    const float* w1 = (const float*)d_in[2];
    const float* w2 = (const float*)d_in[3];
    const float* b0 = (const float*)d_in[4];
    float* out = (float*)d_out;

    cudaFuncSetAttribute(k0_mma, cudaFuncAttributeMaxDynamicSharedMemorySize, K0_SMEM);
    cudaFuncSetAttribute(k1_mma, cudaFuncAttributeMaxDynamicSharedMemorySize, K1_SMEM);
    cudaFuncSetAttribute(k2_mma, cudaFuncAttributeMaxDynamicSharedMemorySize, K2_SMEM);

    k0_mma<<<304, 256, K0_SMEM>>>(x, w0, b0, out);
    k1_mma<<<304, 256, K1_SMEM>>>(x, w1, out);
    k2_mma<<<304, 256, K2_SMEM>>>(x, w2, out);
}